// round 2
// baseline (speedup 1.0000x reference)
#include <cuda_runtime.h>
#include <cuda_bf16.h>
#include <math.h>

// Problem constants
#define B_   4
#define LQ_  8192
#define S_   16384
#define D_   256
#define NH_  8
#define NP_  4
#define DH_  32
#define HH_  128
#define WW_  128
#define NQ_  (B_ * LQ_)   // 32768
#define NS_  (B_ * S_)    // 65536

// ---------------- scratch (static __device__ — no allocations) ----------------
__device__ float g_value[(size_t)NS_ * D_];       // 64 MB  [B,S,NH,DH]
__device__ float g_offattn[(size_t)NQ_ * 96];     // 12 MB  [NQ, 64 off | 32 attn]
__device__ float g_sampled[(size_t)NQ_ * D_];     // 32 MB
__device__ float g_attnout[(size_t)NQ_ * D_];     // 32 MB
__device__ float g_Woa[256 * 96];
__device__ float g_boa[96];

// ---------------- pack W_off | W_attn into one [256,96] weight ----------------
__global__ void pack_w_kernel(const float* __restrict__ Woff, const float* __restrict__ boff,
                              const float* __restrict__ Wattn, const float* __restrict__ battn) {
    int i = blockIdx.x * blockDim.x + threadIdx.x;
    if (i < 256 * 96) {
        int r = i / 96, c = i % 96;
        g_Woa[i] = (c < 64) ? Woff[r * 64 + c] : Wattn[r * 32 + (c - 64)];
    }
    if (i < 96) g_boa[i] = (i < 64) ? boff[i] : battn[i - 64];
}

// ---------------- fp32 tiled GEMM: C[M,N] = A[M,K] @ B[K,N] + bias ----------------
// BM=128, BN=128, BK=8, 256 threads, 8x8 per thread.
// Requirements: M % 128 == 0, K % 8 == 0, N % 4 == 0. N guarded.
#define GBM 128
#define GBN 128
#define GBK 8

__global__ __launch_bounds__(256, 2)
void sgemm_bias(const float* __restrict__ A, const float* __restrict__ Bm,
                const float* __restrict__ bias, float* __restrict__ C,
                int M, int N, int K) {
    __shared__ float As[GBK][GBM + 4];
    __shared__ float Bs[GBK][GBN];

    int tid  = threadIdx.x;
    int row0 = blockIdx.y * GBM;
    int col0 = blockIdx.x * GBN;

    int ar = tid >> 1;            // 0..127 (A tile row)
    int ak = (tid & 1) << 2;      // 0 or 4 (A tile k)
    int bk = tid >> 5;            // 0..7   (B tile k)
    int bc = (tid & 31) << 2;     // 0..124 (B tile col)

    int crow = (tid >> 4) * 8;    // 0..120
    int ccol = (tid & 15) * 8;    // 0..120

    float acc[8][8];
#pragma unroll
    for (int i = 0; i < 8; i++)
#pragma unroll
        for (int j = 0; j < 8; j++) acc[i][j] = 0.f;

    for (int k0 = 0; k0 < K; k0 += GBK) {
        float4 av = *(const float4*)(A + (size_t)(row0 + ar) * K + k0 + ak);
        float4 bv = make_float4(0.f, 0.f, 0.f, 0.f);
        if (col0 + bc < N)
            bv = *(const float4*)(Bm + (size_t)(k0 + bk) * N + col0 + bc);
        As[ak + 0][ar] = av.x;
        As[ak + 1][ar] = av.y;
        As[ak + 2][ar] = av.z;
        As[ak + 3][ar] = av.w;
        *(float4*)&Bs[bk][bc] = bv;
        __syncthreads();
#pragma unroll
        for (int k = 0; k < GBK; k++) {
            float ra[8], rb[8];
#pragma unroll
            for (int i = 0; i < 8; i++) ra[i] = As[k][crow + i];
#pragma unroll
            for (int j = 0; j < 8; j++) rb[j] = Bs[k][ccol + j];
#pragma unroll
            for (int i = 0; i < 8; i++)
#pragma unroll
                for (int j = 0; j < 8; j++)
                    acc[i][j] = fmaf(ra[i], rb[j], acc[i][j]);
        }
        __syncthreads();
    }

#pragma unroll
    for (int i = 0; i < 8; i++) {
        int r = row0 + crow + i;
#pragma unroll
        for (int j = 0; j < 8; j += 4) {
            int c = col0 + ccol + j;
            if (c < N) {
                float4 o;
                o.x = acc[i][j + 0] + bias[c + 0];
                o.y = acc[i][j + 1] + bias[c + 1];
                o.z = acc[i][j + 2] + bias[c + 2];
                o.w = acc[i][j + 3] + bias[c + 3];
                *(float4*)(C + (size_t)r * N + c) = o;
            }
        }
    }
}

// ---------------- deformable bilinear sampling ----------------
// grid = NQ blocks, 256 threads: warp h handles head h, lane = DH channel.
__global__ __launch_bounds__(256)
void sample_kernel(const float* __restrict__ refp) {
    int q    = blockIdx.x;            // 0..NQ-1
    int h    = threadIdx.x >> 5;      // 0..7
    int lane = threadIdx.x & 31;
    int b    = q >> 13;               // q / LQ_  (LQ_=8192)

    const float* oa = g_offattn + (size_t)q * 96;
    float rx = refp[q * 2 + 0];
    float ry = refp[q * 2 + 1];

    // softmax over the 4 attn logits of this head
    float a0 = oa[64 + h * 4 + 0];
    float a1 = oa[64 + h * 4 + 1];
    float a2 = oa[64 + h * 4 + 2];
    float a3 = oa[64 + h * 4 + 3];
    float mx = fmaxf(fmaxf(a0, a1), fmaxf(a2, a3));
    float e0 = expf(a0 - mx), e1 = expf(a1 - mx), e2 = expf(a2 - mx), e3 = expf(a3 - mx);
    float inv = 1.f / (e0 + e1 + e2 + e3);
    float aw[4] = {e0 * inv, e1 * inv, e2 * inv, e3 * inv};

    const float* vb = g_value + (size_t)b * S_ * D_;
    float acc = 0.f;

#pragma unroll
    for (int p = 0; p < NP_; p++) {
        float ox = oa[h * 8 + p * 2 + 0];
        float oy = oa[h * 8 + p * 2 + 1];
        // loc*size - 0.5 with normalizer [W,H]: x = rx*W + ox - 0.5
        float xf = rx * (float)WW_ + ox - 0.5f;
        float yf = ry * (float)HH_ + oy - 0.5f;
        float x0f = floorf(xf), y0f = floorf(yf);
        int x0 = (int)x0f, y0 = (int)y0f;
        float wx1 = xf - x0f, wy1 = yf - y0f;
        float wx0 = 1.f - wx1, wy0 = 1.f - wy1;
        float w00 = wy0 * wx0 * aw[p];
        float w01 = wy0 * wx1 * aw[p];
        float w10 = wy1 * wx0 * aw[p];
        float w11 = wy1 * wx1 * aw[p];
        int x1 = x0 + 1, y1 = y0 + 1;
        int ch = h * DH_ + lane;
        if ((unsigned)y0 < (unsigned)HH_) {
            if ((unsigned)x0 < (unsigned)WW_)
                acc += w00 * vb[((size_t)(y0 * WW_ + x0)) * D_ + ch];
            if ((unsigned)x1 < (unsigned)WW_)
                acc += w01 * vb[((size_t)(y0 * WW_ + x1)) * D_ + ch];
        }
        if ((unsigned)y1 < (unsigned)HH_) {
            if ((unsigned)x0 < (unsigned)WW_)
                acc += w10 * vb[((size_t)(y1 * WW_ + x0)) * D_ + ch];
            if ((unsigned)x1 < (unsigned)WW_)
                acc += w11 * vb[((size_t)(y1 * WW_ + x1)) * D_ + ch];
        }
    }
    g_sampled[(size_t)q * D_ + h * DH_ + lane] = acc;
}

// ---------------- fused residual + LayerNorm over 256-wide rows ----------------
// x = A[row] + Bp[row]; out = (x - mean) * rsqrt(var + 1e-5) * g + b
// one warp per row; lane handles float4 index lane and lane+32.
__global__ __launch_bounds__(256)
void ln_fused(const float* __restrict__ A, const float* __restrict__ Bp,
              const float* __restrict__ g, const float* __restrict__ bb,
              float* __restrict__ out, int rows) {
    int w = (blockIdx.x * blockDim.x + threadIdx.x) >> 5;
    if (w >= rows) return;
    int lane = threadIdx.x & 31;

    const float4* A4 = (const float4*)A + (size_t)w * 64;
    const float4* B4 = (const float4*)Bp + (size_t)w * 64;

    float4 xa = A4[lane];
    float4 xb = B4[lane];
    float4 ya = A4[lane + 32];
    float4 yb = B4[lane + 32];
    float4 x = make_float4(xa.x + xb.x, xa.y + xb.y, xa.z + xb.z, xa.w + xb.w);
    float4 y = make_float4(ya.x + yb.x, ya.y + yb.y, ya.z + yb.z, ya.w + yb.w);

    float s  = x.x + x.y + x.z + x.w + y.x + y.y + y.z + y.w;
    float ss = x.x * x.x + x.y * x.y + x.z * x.z + x.w * x.w
             + y.x * y.x + y.y * y.y + y.z * y.z + y.w * y.w;
#pragma unroll
    for (int o = 16; o > 0; o >>= 1) {
        s  += __shfl_xor_sync(0xffffffffu, s, o);
        ss += __shfl_xor_sync(0xffffffffu, ss, o);
    }
    float m   = s * (1.f / 256.f);
    float var = ss * (1.f / 256.f) - m * m;
    float rs  = rsqrtf(var + 1e-5f);

    const float4* g4 = (const float4*)g;
    const float4* b4 = (const float4*)bb;
    float4 g0 = g4[lane], g1 = g4[lane + 32];
    float4 c0 = b4[lane], c1 = b4[lane + 32];

    float4 o0, o1;
    o0.x = (x.x - m) * rs * g0.x + c0.x;
    o0.y = (x.y - m) * rs * g0.y + c0.y;
    o0.z = (x.z - m) * rs * g0.z + c0.z;
    o0.w = (x.w - m) * rs * g0.w + c0.w;
    o1.x = (y.x - m) * rs * g1.x + c1.x;
    o1.y = (y.y - m) * rs * g1.y + c1.y;
    o1.z = (y.z - m) * rs * g1.z + c1.z;
    o1.w = (y.w - m) * rs * g1.w + c1.w;

    float4* O4 = (float4*)out + (size_t)w * 64;
    O4[lane]      = o0;
    O4[lane + 32] = o1;
}

// ---------------- launch ----------------
extern "C" void kernel_launch(void* const* d_in, const int* in_sizes, int n_in,
                              void* d_out, int out_size) {
    const float* tgt    = (const float*)d_in[0];
    const float* src    = (const float*)d_in[1];
    const float* refp   = (const float*)d_in[2];
    const float* Wv     = (const float*)d_in[3];
    const float* bv     = (const float*)d_in[4];
    const float* Woff   = (const float*)d_in[5];
    const float* boff   = (const float*)d_in[6];
    const float* Wattn  = (const float*)d_in[7];
    const float* battn  = (const float*)d_in[8];
    const float* Wout   = (const float*)d_in[9];
    const float* bout   = (const float*)d_in[10];
    const float* ln1g   = (const float*)d_in[11];
    const float* ln1b   = (const float*)d_in[12];
    const float* ln2g   = (const float*)d_in[13];
    const float* ln2b   = (const float*)d_in[14];

    float* out = (float*)d_out;

    float *p_value, *p_offattn, *p_sampled, *p_attnout, *p_Woa, *p_boa;
    cudaGetSymbolAddress((void**)&p_value,   g_value);
    cudaGetSymbolAddress((void**)&p_offattn, g_offattn);
    cudaGetSymbolAddress((void**)&p_sampled, g_sampled);
    cudaGetSymbolAddress((void**)&p_attnout, g_attnout);
    cudaGetSymbolAddress((void**)&p_Woa,     g_Woa);
    cudaGetSymbolAddress((void**)&p_boa,     g_boa);

    // 0) pack off/attn weights
    pack_w_kernel<<<(256 * 96 + 255) / 256, 256>>>(Woff, boff, Wattn, battn);

    // 1) value = src @ W_value + b_value   [65536,256]x[256,256]
    {
        dim3 grid((D_ + GBN - 1) / GBN, NS_ / GBM);
        sgemm_bias<<<grid, 256>>>(src, Wv, bv, p_value, NS_, D_, D_);
    }

    // 2) off|attn = tgt @ [W_off|W_attn] + bias   [32768,96]
    {
        dim3 grid(1, NQ_ / GBM);
        sgemm_bias<<<grid, 256>>>(tgt, p_Woa, p_boa, p_offattn, NQ_, 96, D_);
    }

    // 3) deformable sampling -> g_sampled [32768,256]
    sample_kernel<<<NQ_, 256>>>(refp);

    // 4) attn_out = sampled @ W_out + b_out   [32768,256]x[256,256]
    {
        dim3 grid((D_ + GBN - 1) / GBN, NQ_ / GBM);
        sgemm_bias<<<grid, 256>>>(p_sampled, Wout, bout, p_attnout, NQ_, D_, D_);
    }

    // 5) query = LN(tgt + attn_out) -> out[0 : NQ*D]
    {
        int rows = NQ_;
        int blocks = (rows * 32 + 255) / 256;
        ln_fused<<<blocks, 256>>>(tgt, p_attnout, ln1g, ln1b, out, rows);
    }

    // 6) src_out = LN(src + src) -> out[NQ*D : NQ*D + NS*D]
    {
        int rows = NS_;
        int blocks = (rows * 32 + 255) / 256;
        ln_fused<<<blocks, 256>>>(src, src, ln2g, ln2b, out + (size_t)NQ_ * D_, rows);
    }
}

// round 6
// speedup vs baseline: 2.8501x; 2.8501x over previous
#include <cuda_runtime.h>
#include <cuda_bf16.h>
#include <cstdint>
#include <math.h>

// Problem constants
#define B_   4
#define LQ_  8192
#define S_   16384
#define D_   256
#define NH_  8
#define NP_  4
#define DH_  32
#define HH_  128
#define WW_  128
#define NQ_  (B_ * LQ_)   // 32768
#define NS_  (B_ * S_)    // 65536

// ---------------- scratch (static __device__ — no allocations) ----------------
__device__ float g_value[(size_t)NS_ * D_];       // 64 MB
__device__ float g_offattn[(size_t)NQ_ * 96];     // 12 MB
__device__ float g_sampled[(size_t)NQ_ * D_];     // 32 MB
__device__ float g_attnout[(size_t)NQ_ * D_];     // 32 MB
__device__ float g_Woa[256 * 96];
__device__ float g_boa[96];

// ---------------- pack W_off | W_attn into one [256,96] weight ----------------
__global__ void pack_w_kernel(const float* __restrict__ Woff, const float* __restrict__ boff,
                              const float* __restrict__ Wattn, const float* __restrict__ battn) {
    int i = blockIdx.x * blockDim.x + threadIdx.x;
    if (i < 256 * 96) {
        int r = i / 96, c = i % 96;
        g_Woa[i] = (c < 64) ? Woff[r * 64 + c] : Wattn[r * 32 + (c - 64)];
    }
    if (i < 96) g_boa[i] = (i < 64) ? boff[i] : battn[i - 64];
}

// ================= tf32 tensor-core GEMM =================
// C[M,N] = A[M,K] @ B[K,N] + bias, fp32 in/out, tf32 mma.m16n8k8 accum fp32.
// Block 128x128x32, 256 threads (8 warps, 2x4), warp tile 64x32.
// Requirements: M%128==0, K%32==0. N guarded (multiple of 4).
#define TBM 128
#define TBN 128
#define TBK 32
#define A_LD 36     // 128 rows x 36 floats (pad 4)
#define B_LD 136    // 32 k-rows x 136 floats (pad 8)
#define ASZ (TBM * A_LD)         // 4608 floats
#define BSZ (TBK * B_LD)         // 4352 floats
#define STAGE_SZ (ASZ + BSZ)     // 8960 floats
#define GEMM_SMEM_BYTES (2 * STAGE_SZ * 4)   // 71680 B

__device__ __forceinline__ void cp16(float* dst_s, const float* src_g, int sz) {
    unsigned int d = (unsigned int)__cvta_generic_to_shared(dst_s);
    asm volatile("cp.async.ca.shared.global [%0], [%1], 16, %2;\n"
                 :: "r"(d), "l"(src_g), "r"(sz));
}

__device__ __forceinline__ void load_tiles(float* As, float* Bs,
                                           const float* __restrict__ A,
                                           const float* __restrict__ B,
                                           int N, int K, int row0, int col0, int k0, int tid) {
#pragma unroll
    for (int it = 0; it < 4; it++) {           // A: 128 rows x 8 quads
        int idx = it * 256 + tid;
        int r = idx >> 3;
        int kq = (idx & 7) << 2;
        cp16(As + r * A_LD + kq, A + (size_t)(row0 + r) * K + k0 + kq, 16);
    }
#pragma unroll
    for (int it = 0; it < 4; it++) {           // B: 32 k-rows x 32 quads
        int idx = it * 256 + tid;
        int r = idx >> 5;
        int nq = (idx & 31) << 2;
        int sz = (col0 + nq < N) ? 16 : 0;
        cp16(Bs + r * B_LD + nq, B + (size_t)(k0 + r) * N + (col0 + nq < N ? col0 + nq : 0), sz);
    }
    asm volatile("cp.async.commit_group;\n");
}

__device__ __forceinline__ void mma_tf32(float* d, const float* a, const float* b) {
    const unsigned int* A = reinterpret_cast<const unsigned int*>(a);
    const unsigned int* Bv = reinterpret_cast<const unsigned int*>(b);
    asm volatile("mma.sync.aligned.m16n8k8.row.col.f32.tf32.tf32.f32 "
                 "{%0,%1,%2,%3}, {%4,%5,%6,%7}, {%8,%9}, {%0,%1,%2,%3};\n"
                 : "+f"(d[0]), "+f"(d[1]), "+f"(d[2]), "+f"(d[3])
                 : "r"(A[0]), "r"(A[1]), "r"(A[2]), "r"(A[3]), "r"(Bv[0]), "r"(Bv[1]));
}

__global__ __launch_bounds__(256)
void gemm_tf32(const float* __restrict__ A, const float* __restrict__ Bm,
               const float* __restrict__ bias, float* __restrict__ C,
               int M, int N, int K) {
    extern __shared__ float sm[];
    int tid  = threadIdx.x;
    int lane = tid & 31;
    int wid  = tid >> 5;
    int g    = lane >> 2;       // 0..7
    int tig  = lane & 3;        // 0..3
    int wm   = wid >> 2;        // 0..1
    int wn   = wid & 3;         // 0..3
    int row0 = blockIdx.y * TBM;
    int col0 = blockIdx.x * TBN;

    float acc[4][4][4];
#pragma unroll
    for (int mi = 0; mi < 4; mi++)
#pragma unroll
        for (int ni = 0; ni < 4; ni++)
#pragma unroll
            for (int e = 0; e < 4; e++) acc[mi][ni][e] = 0.f;

    int nk = K / TBK;
    load_tiles(sm, sm + ASZ, A, Bm, N, K, row0, col0, 0, tid);

    for (int kt = 0; kt < nk; kt++) {
        asm volatile("cp.async.wait_group 0;\n");
        __syncthreads();
        if (kt + 1 < nk) {
            int st = (kt + 1) & 1;
            load_tiles(sm + st * STAGE_SZ, sm + st * STAGE_SZ + ASZ,
                       A, Bm, N, K, row0, col0, (kt + 1) * TBK, tid);
        }
        const float* As = sm + (kt & 1) * STAGE_SZ;
        const float* Bs = As + ASZ;

#pragma unroll
        for (int ks = 0; ks < 4; ks++) {
            float af[4][4];
#pragma unroll
            for (int mi = 0; mi < 4; mi++) {
                const float* ap = As + (wm * 64 + mi * 16 + g) * A_LD + ks * 8 + tig;
                af[mi][0] = ap[0];
                af[mi][1] = ap[8 * A_LD];
                af[mi][2] = ap[4];
                af[mi][3] = ap[8 * A_LD + 4];
            }
            float bf[4][2];
#pragma unroll
            for (int ni = 0; ni < 4; ni++) {
                const float* bp = Bs + (ks * 8 + tig) * B_LD + wn * 32 + ni * 8 + g;
                bf[ni][0] = bp[0];
                bf[ni][1] = bp[4 * B_LD];
            }
#pragma unroll
            for (int mi = 0; mi < 4; mi++)
#pragma unroll
                for (int ni = 0; ni < 4; ni++)
                    mma_tf32(acc[mi][ni], af[mi], bf[ni]);
        }
        __syncthreads();
    }

    // epilogue: bias + store
    float bc[4][2];
#pragma unroll
    for (int ni = 0; ni < 4; ni++) {
        int c = col0 + wn * 32 + ni * 8 + 2 * tig;
        bc[ni][0] = (c < N) ? bias[c] : 0.f;
        bc[ni][1] = (c < N) ? bias[c + 1] : 0.f;
    }
#pragma unroll
    for (int mi = 0; mi < 4; mi++) {
        int r = row0 + wm * 64 + mi * 16 + g;
#pragma unroll
        for (int ni = 0; ni < 4; ni++) {
            int c = col0 + wn * 32 + ni * 8 + 2 * tig;
            if (c < N) {
                float2 o0 = make_float2(acc[mi][ni][0] + bc[ni][0], acc[mi][ni][1] + bc[ni][1]);
                float2 o1 = make_float2(acc[mi][ni][2] + bc[ni][0], acc[mi][ni][3] + bc[ni][1]);
                *(float2*)(C + (size_t)r * N + c)       = o0;
                *(float2*)(C + (size_t)(r + 8) * N + c) = o1;
            }
        }
    }
}

// ---------------- deformable bilinear sampling (float4 channels) ----------------
// 256 threads = 4 queries; per query: 8 heads x 8 threads, each thread 4 channels.
__global__ __launch_bounds__(256)
void sample_kernel(const float* __restrict__ refp) {
    int t  = threadIdx.x;
    int q  = blockIdx.x * 4 + (t >> 6);
    int h  = (t >> 3) & 7;
    int ci = (t & 7) << 2;
    int b  = q >> 13;            // q / LQ_

    const float* oa = g_offattn + (size_t)q * 96;
    float rx = refp[q * 2 + 0];
    float ry = refp[q * 2 + 1];

    float a0 = oa[64 + h * 4 + 0];
    float a1 = oa[64 + h * 4 + 1];
    float a2 = oa[64 + h * 4 + 2];
    float a3 = oa[64 + h * 4 + 3];
    float mx = fmaxf(fmaxf(a0, a1), fmaxf(a2, a3));
    float e0 = expf(a0 - mx), e1 = expf(a1 - mx), e2 = expf(a2 - mx), e3 = expf(a3 - mx);
    float inv = 1.f / (e0 + e1 + e2 + e3);
    float aw[4] = {e0 * inv, e1 * inv, e2 * inv, e3 * inv};

    const float* vb = g_value + (size_t)b * S_ * D_ + h * DH_ + ci;
    float4 acc = make_float4(0.f, 0.f, 0.f, 0.f);

#pragma unroll
    for (int p = 0; p < NP_; p++) {
        float ox = oa[h * 8 + p * 2 + 0];
        float oy = oa[h * 8 + p * 2 + 1];
        float xf = rx * (float)WW_ + ox - 0.5f;
        float yf = ry * (float)HH_ + oy - 0.5f;
        float x0f = floorf(xf), y0f = floorf(yf);
        int x0 = (int)x0f, y0 = (int)y0f;
        float wx1 = xf - x0f, wy1 = yf - y0f;
        float wx0 = 1.f - wx1, wy0 = 1.f - wy1;
        float w00 = wy0 * wx0 * aw[p];
        float w01 = wy0 * wx1 * aw[p];
        float w10 = wy1 * wx0 * aw[p];
        float w11 = wy1 * wx1 * aw[p];
        int x1 = x0 + 1, y1 = y0 + 1;
        bool xin0 = (unsigned)x0 < (unsigned)WW_;
        bool xin1 = (unsigned)x1 < (unsigned)WW_;
        if ((unsigned)y0 < (unsigned)HH_) {
            if (xin0) {
                float4 v = *(const float4*)(vb + (size_t)(y0 * WW_ + x0) * D_);
                acc.x += w00 * v.x; acc.y += w00 * v.y; acc.z += w00 * v.z; acc.w += w00 * v.w;
            }
            if (xin1) {
                float4 v = *(const float4*)(vb + (size_t)(y0 * WW_ + x1) * D_);
                acc.x += w01 * v.x; acc.y += w01 * v.y; acc.z += w01 * v.z; acc.w += w01 * v.w;
            }
        }
        if ((unsigned)y1 < (unsigned)HH_) {
            if (xin0) {
                float4 v = *(const float4*)(vb + (size_t)(y1 * WW_ + x0) * D_);
                acc.x += w10 * v.x; acc.y += w10 * v.y; acc.z += w10 * v.z; acc.w += w10 * v.w;
            }
            if (xin1) {
                float4 v = *(const float4*)(vb + (size_t)(y1 * WW_ + x1) * D_);
                acc.x += w11 * v.x; acc.y += w11 * v.y; acc.z += w11 * v.z; acc.w += w11 * v.w;
            }
        }
    }
    *(float4*)(g_sampled + (size_t)q * D_ + h * DH_ + ci) = acc;
}

// ---------------- fused residual + LayerNorm over 256-wide rows ----------------
__global__ __launch_bounds__(256)
void ln_fused(const float* __restrict__ A, const float* __restrict__ Bp,
              const float* __restrict__ g, const float* __restrict__ bb,
              float* __restrict__ out, int rows) {
    int w = (blockIdx.x * blockDim.x + threadIdx.x) >> 5;
    if (w >= rows) return;
    int lane = threadIdx.x & 31;

    const float4* A4 = (const float4*)A + (size_t)w * 64;
    const float4* B4 = (const float4*)Bp + (size_t)w * 64;

    float4 xa = A4[lane];
    float4 xb = B4[lane];
    float4 ya = A4[lane + 32];
    float4 yb = B4[lane + 32];
    float4 x = make_float4(xa.x + xb.x, xa.y + xb.y, xa.z + xb.z, xa.w + xb.w);
    float4 y = make_float4(ya.x + yb.x, ya.y + yb.y, ya.z + yb.z, ya.w + yb.w);

    float s  = x.x + x.y + x.z + x.w + y.x + y.y + y.z + y.w;
    float ss = x.x * x.x + x.y * x.y + x.z * x.z + x.w * x.w
             + y.x * y.x + y.y * y.y + y.z * y.z + y.w * y.w;
#pragma unroll
    for (int o = 16; o > 0; o >>= 1) {
        s  += __shfl_xor_sync(0xffffffffu, s, o);
        ss += __shfl_xor_sync(0xffffffffu, ss, o);
    }
    float m   = s * (1.f / 256.f);
    float var = ss * (1.f / 256.f) - m * m;
    float rs  = rsqrtf(var + 1e-5f);

    const float4* g4 = (const float4*)g;
    const float4* b4 = (const float4*)bb;
    float4 g0 = g4[lane], g1 = g4[lane + 32];
    float4 c0 = b4[lane], c1 = b4[lane + 32];

    float4 o0, o1;
    o0.x = (x.x - m) * rs * g0.x + c0.x;
    o0.y = (x.y - m) * rs * g0.y + c0.y;
    o0.z = (x.z - m) * rs * g0.z + c0.z;
    o0.w = (x.w - m) * rs * g0.w + c0.w;
    o1.x = (y.x - m) * rs * g1.x + c1.x;
    o1.y = (y.y - m) * rs * g1.y + c1.y;
    o1.z = (y.z - m) * rs * g1.z + c1.z;
    o1.w = (y.w - m) * rs * g1.w + c1.w;

    float4* O4 = (float4*)out + (size_t)w * 64;
    O4[lane]      = o0;
    O4[lane + 32] = o1;
}

// ---------------- launch ----------------
extern "C" void kernel_launch(void* const* d_in, const int* in_sizes, int n_in,
                              void* d_out, int out_size) {
    const float* tgt    = (const float*)d_in[0];
    const float* src    = (const float*)d_in[1];
    const float* refp   = (const float*)d_in[2];
    const float* Wv     = (const float*)d_in[3];
    const float* bv     = (const float*)d_in[4];
    const float* Woff   = (const float*)d_in[5];
    const float* boff   = (const float*)d_in[6];
    const float* Wattn  = (const float*)d_in[7];
    const float* battn  = (const float*)d_in[8];
    const float* Wout   = (const float*)d_in[9];
    const float* bout   = (const float*)d_in[10];
    const float* ln1g   = (const float*)d_in[11];
    const float* ln1b   = (const float*)d_in[12];
    const float* ln2g   = (const float*)d_in[13];
    const float* ln2b   = (const float*)d_in[14];

    float* out = (float*)d_out;

    float *p_value, *p_offattn, *p_sampled, *p_attnout, *p_Woa, *p_boa;
    cudaGetSymbolAddress((void**)&p_value,   g_value);
    cudaGetSymbolAddress((void**)&p_offattn, g_offattn);
    cudaGetSymbolAddress((void**)&p_sampled, g_sampled);
    cudaGetSymbolAddress((void**)&p_attnout, g_attnout);
    cudaGetSymbolAddress((void**)&p_Woa,     g_Woa);
    cudaGetSymbolAddress((void**)&p_boa,     g_boa);

    // No static guards (harness rule): unconditional, idempotent, not a stream op.
    cudaFuncSetAttribute(gemm_tf32, cudaFuncAttributeMaxDynamicSharedMemorySize,
                         GEMM_SMEM_BYTES);

    // 0) pack off/attn weights
    pack_w_kernel<<<(256 * 96 + 255) / 256, 256>>>(Woff, boff, Wattn, battn);

    // 1) value = src @ W_value + b_value   [65536,256]
    {
        dim3 grid(D_ / TBN, NS_ / TBM);
        gemm_tf32<<<grid, 256, GEMM_SMEM_BYTES>>>(src, Wv, bv, p_value, NS_, D_, D_);
    }

    // 2) off|attn = tgt @ [W_off|W_attn] + bias   [32768,96]
    {
        dim3 grid(1, NQ_ / TBM);
        gemm_tf32<<<grid, 256, GEMM_SMEM_BYTES>>>(tgt, p_Woa, p_boa, p_offattn, NQ_, 96, D_);
    }

    // 3) deformable sampling -> g_sampled [32768,256]
    sample_kernel<<<NQ_ / 4, 256>>>(refp);

    // 4) attn_out = sampled @ W_out + b_out   [32768,256]
    {
        dim3 grid(D_ / TBN, NQ_ / TBM);
        gemm_tf32<<<grid, 256, GEMM_SMEM_BYTES>>>(p_sampled, Wout, bout, p_attnout, NQ_, D_, D_);
    }

    // 5) query = LN(tgt + attn_out) -> out[0 : NQ*D]
    ln_fused<<<(NQ_ * 32 + 255) / 256, 256>>>(tgt, p_attnout, ln1g, ln1b, out, NQ_);

    // 6) src_out = LN(src + src) -> out[NQ*D : ...]
    ln_fused<<<(NS_ * 32 + 255) / 256, 256>>>(src, src, ln2g, ln2b, out + (size_t)NQ_ * D_, NS_);
}